// round 1
// baseline (speedup 1.0000x reference)
#include <cuda_runtime.h>
#include <cuda_bf16.h>
#include <math.h>

#define N_NODES 100000
#define N_EDGES 260000
#define BGRAPH  4096
#define H       300
#define H2      600
#define LAYERS  5
#define FE      16
#define BN_EPS  1e-5f

// ---------------- device scratch (static; no runtime allocation) --------------
__device__ float g_x[N_NODES * H];     // h / x (h_list[l] after vfeat add)
__device__ float g_hp[N_NODES * H];    // x @ Wn + bn_lin
__device__ float g_acc[N_NODES * H];   // res init + edge scatter accumulation
__device__ float g_deg[N_NODES];
__device__ float g_vfeat[BGRAPH * H];
__device__ float g_vtmp[BGRAPH * H];
__device__ float g_z1[BGRAPH * H2];
__device__ float g_z2[BGRAPH * H];
__device__ float g_sum[H2];
__device__ float g_sumsq[H2];
__device__ float g_mean[H2];
__device__ float g_rstd[H2];

// ---------------- small elementwise / init kernels ---------------------------

__global__ void k_deg_init() {
    int i = blockIdx.x * blockDim.x + threadIdx.x;
    if (i < N_NODES) g_deg[i] = 1.0f;
}

__global__ void k_deg_count(const int* __restrict__ dst) {
    int e = blockIdx.x * blockDim.x + threadIdx.x;
    if (e < N_EDGES) atomicAdd(&g_deg[dst[e]], 1.0f);
}

__global__ void k_init_h(const float* __restrict__ node_emb,
                         const int* __restrict__ node_types) {
    int idx = blockIdx.x * blockDim.x + threadIdx.x;
    if (idx < N_NODES * H) {
        int n = idx / H, j = idx - n * H;
        g_x[idx] = node_emb[node_types[n] * H + j];
    }
}

__global__ void k_init_vfeat(const float* __restrict__ vn_emb) {
    int idx = blockIdx.x * blockDim.x + threadIdx.x;
    if (idx < BGRAPH * H) g_vfeat[idx] = vn_emb[idx % H];
}

// x = h + vfeat[gid[n]]
__global__ void k_addv(const int* __restrict__ gid) {
    int idx = blockIdx.x * blockDim.x + threadIdx.x;
    if (idx < N_NODES * H) {
        int n = idx / H, j = idx - n * H;
        g_x[idx] += g_vfeat[gid[n] * H + j];
    }
}

// vtmp = vfeat (copy)
__global__ void k_vtmp_init() {
    int idx = blockIdx.x * blockDim.x + threadIdx.x;
    if (idx < BGRAPH * H) g_vtmp[idx] = g_vfeat[idx];
}

// vtmp[gid[n]] += x[n]
__global__ void k_vseg(const int* __restrict__ gid) {
    int idx = blockIdx.x * blockDim.x + threadIdx.x;
    if (idx < N_NODES * H) {
        int n = idx / H, j = idx - n * H;
        atomicAdd(&g_vtmp[gid[n] * H + j], g_x[idx]);
    }
}

// acc = relu(hp + res_emb) / deg
__global__ void k_resinit(const float* __restrict__ res_emb_l) {
    int idx = blockIdx.x * blockDim.x + threadIdx.x;
    if (idx < N_NODES * H) {
        int n = idx / H, j = idx - n * H;
        g_acc[idx] = fmaxf(g_hp[idx] + res_emb_l[j], 0.0f) / g_deg[n];
    }
}

// ---------------- fused edge kernel -------------------------------------------
// For each edge: ep = edge_feats[e] @ We_l + be_l (computed on the fly, We in smem),
// v = norm * relu(hp[src] + ep), atomicAdd into acc[dst].
__global__ void k_edge(const float* __restrict__ ef,
                       const float* __restrict__ We_l,
                       const float* __restrict__ be_l,
                       const int* __restrict__ src,
                       const int* __restrict__ dst) {
    __shared__ float Ws[FE * H];
    __shared__ float Bs[H];
    for (int i = threadIdx.x; i < FE * H; i += blockDim.x) Ws[i] = We_l[i];
    for (int i = threadIdx.x; i < H; i += blockDim.x) Bs[i] = be_l[i];
    __syncthreads();

    int lane = threadIdx.x & 31;
    int warp = (blockIdx.x * blockDim.x + threadIdx.x) >> 5;
    int nwarps = (gridDim.x * blockDim.x) >> 5;

    for (int e = warp; e < N_EDGES; e += nwarps) {
        int s = src[e], d = dst[e];
        float nrm = rsqrtf(g_deg[s] * g_deg[d]);
        float efv[FE];
#pragma unroll
        for (int k = 0; k < FE; k++) efv[k] = __ldg(&ef[e * FE + k]);
        const float* hps = &g_hp[s * H];
        float* accd = &g_acc[d * H];
        for (int j = lane; j < H; j += 32) {
            float ep = Bs[j];
#pragma unroll
            for (int k = 0; k < FE; k++) ep = fmaf(efv[k], Ws[k * H + j], ep);
            float v = nrm * fmaxf(hps[j] + ep, 0.0f);
            atomicAdd(&accd[j], v);
        }
    }
}

// ---------------- batch norm -------------------------------------------------

__global__ void k_zero_stats(int cols) {
    int c = blockIdx.x * blockDim.x + threadIdx.x;
    if (c < cols) { g_sum[c] = 0.0f; g_sumsq[c] = 0.0f; }
}

__global__ void k_bnstat(const float* __restrict__ X, int rows, int cols) {
    int r0 = blockIdx.x * 256;
    int rend = min(r0 + 256, rows);
    int t = threadIdx.x;
    float s[3] = {0, 0, 0}, q[3] = {0, 0, 0};
    for (int r = r0; r < rend; r++) {
        const float* row = X + (long)r * cols;
        int ci = 0;
        for (int c = t; c < cols; c += 256, ci++) {
            float v = row[c];
            s[ci] += v; q[ci] += v * v;
        }
    }
    int ci = 0;
    for (int c = t; c < cols; c += 256, ci++) {
        atomicAdd(&g_sum[c], s[ci]);
        atomicAdd(&g_sumsq[c], q[ci]);
    }
}

__global__ void k_bnfinal(int rows, int cols) {
    int c = blockIdx.x * blockDim.x + threadIdx.x;
    if (c < cols) {
        float m = g_sum[c] / (float)rows;
        float v = g_sumsq[c] / (float)rows - m * m;
        g_mean[c] = m;
        g_rstd[c] = rsqrtf(v + BN_EPS);
    }
}

__global__ void k_bnapply(const float* __restrict__ X, float* __restrict__ Y,
                          const float* __restrict__ gamma,
                          const float* __restrict__ beta,
                          int rows, int cols, int do_relu) {
    int idx = blockIdx.x * blockDim.x + threadIdx.x;
    if (idx < rows * cols) {
        int c = idx % cols;
        float v = (X[idx] - g_mean[c]) * g_rstd[c] * gamma[c] + beta[c];
        if (do_relu) v = fmaxf(v, 0.0f);
        Y[idx] = v;
    }
}

// ---------------- SGEMM: C[M,Ncol] = A[M,K] @ W[K,Ncol] + bias ----------------
__global__ __launch_bounds__(256, 2)
void sgemm_bias(const float* __restrict__ A, const float* __restrict__ W,
                const float* __restrict__ bias, float* __restrict__ C,
                int M, int K, int Ncol) {
    const int BM = 128, BN = 128, BK = 8;
    __shared__ float As[BK][BM];
    __shared__ float Bs[BK][BN];
    int tid = threadIdx.x;
    int m0 = blockIdx.y * BM, n0 = blockIdx.x * BN;
    int tx = tid & 15, ty = tid >> 4;
    float acc[8][8];
#pragma unroll
    for (int i = 0; i < 8; i++)
#pragma unroll
        for (int j = 0; j < 8; j++) acc[i][j] = 0.0f;

    for (int k0 = 0; k0 < K; k0 += BK) {
#pragma unroll
        for (int i = 0; i < 4; i++) {
            int idx = tid * 4 + i;
            int r = idx >> 3, c = idx & 7;
            int gm = m0 + r, gk = k0 + c;
            As[c][r] = (gm < M && gk < K) ? A[(long)gm * K + gk] : 0.0f;
        }
#pragma unroll
        for (int i = 0; i < 4; i++) {
            int idx = tid * 4 + i;
            int r = idx >> 7, c = idx & 127;
            int gk = k0 + r, gn = n0 + c;
            Bs[r][c] = (gk < K && gn < Ncol) ? W[(long)gk * Ncol + gn] : 0.0f;
        }
        __syncthreads();
#pragma unroll
        for (int kk = 0; kk < BK; kk++) {
            float ra[8], rb[8];
#pragma unroll
            for (int i = 0; i < 8; i++) ra[i] = As[kk][ty * 8 + i];
#pragma unroll
            for (int j = 0; j < 8; j++) rb[j] = Bs[kk][tx * 8 + j];
#pragma unroll
            for (int i = 0; i < 8; i++)
#pragma unroll
                for (int j = 0; j < 8; j++) acc[i][j] = fmaf(ra[i], rb[j], acc[i][j]);
        }
        __syncthreads();
    }
#pragma unroll
    for (int i = 0; i < 8; i++) {
        int gm = m0 + ty * 8 + i;
        if (gm >= M) continue;
#pragma unroll
        for (int j = 0; j < 8; j++) {
            int gn = n0 + tx * 8 + j;
            if (gn < Ncol) C[(long)gm * Ncol + gn] = acc[i][j] + bias[gn];
        }
    }
}

// ---------------- host orchestration -----------------------------------------

static inline int cdiv(int a, int b) { return (a + b - 1) / b; }

extern "C" void kernel_launch(void* const* d_in, const int* in_sizes, int n_in,
                              void* d_out, int out_size) {
    const int *node_types, *src, *dst, *gid;
    const float *edge_feats, *node_emb, *Wn, *bn_lin, *We, *be, *res_emb,
                *bn_gamma, *bn_beta, *vn_emb, *vW1, *vb1, *vg1, *vbt1,
                *vW2, *vb2, *vg2, *vbt2;

    if (in_sizes[0] == N_NODES) {
        // setup_inputs dict order
        node_types = (const int*)d_in[0];
        edge_feats = (const float*)d_in[1];
        src        = (const int*)d_in[2];
        dst        = (const int*)d_in[3];
        gid        = (const int*)d_in[4];
        // d_in[5] = batch_size (scalar)
        node_emb = (const float*)d_in[6];
        Wn       = (const float*)d_in[7];
        bn_lin   = (const float*)d_in[8];
        We       = (const float*)d_in[9];
        be       = (const float*)d_in[10];
        res_emb  = (const float*)d_in[11];
        bn_gamma = (const float*)d_in[12];
        bn_beta  = (const float*)d_in[13];
        vn_emb   = (const float*)d_in[14];
        vW1  = (const float*)d_in[15];
        vb1  = (const float*)d_in[16];
        vg1  = (const float*)d_in[17];
        vbt1 = (const float*)d_in[18];
        vW2  = (const float*)d_in[19];
        vb2  = (const float*)d_in[20];
        vg2  = (const float*)d_in[21];
        vbt2 = (const float*)d_in[22];
    } else {
        // reference() signature order
        edge_feats = (const float*)d_in[0];
        node_emb = (const float*)d_in[1];
        Wn       = (const float*)d_in[2];
        bn_lin   = (const float*)d_in[3];
        We       = (const float*)d_in[4];
        be       = (const float*)d_in[5];
        res_emb  = (const float*)d_in[6];
        bn_gamma = (const float*)d_in[7];
        bn_beta  = (const float*)d_in[8];
        vn_emb   = (const float*)d_in[9];
        vW1  = (const float*)d_in[10];
        vb1  = (const float*)d_in[11];
        vg1  = (const float*)d_in[12];
        vbt1 = (const float*)d_in[13];
        vW2  = (const float*)d_in[14];
        vb2  = (const float*)d_in[15];
        vg2  = (const float*)d_in[16];
        vbt2 = (const float*)d_in[17];
        node_types = (const int*)d_in[18];
        src        = (const int*)d_in[19];
        dst        = (const int*)d_in[20];
        gid        = (const int*)d_in[21];
    }

    const int NH = N_NODES * H;
    const int BH = BGRAPH * H;
    const int TPB = 256;

    // --- init ---
    k_deg_init<<<cdiv(N_NODES, TPB), TPB>>>();
    k_deg_count<<<cdiv(N_EDGES, TPB), TPB>>>(dst);
    k_init_h<<<cdiv(NH, TPB), TPB>>>(node_emb, node_types);
    k_init_vfeat<<<cdiv(BH, TPB), TPB>>>(vn_emb);

    float* g_x_p;      cudaGetSymbolAddress((void**)&g_x_p, g_x);
    float* g_hp_p;     cudaGetSymbolAddress((void**)&g_hp_p, g_hp);
    float* g_acc_p;    cudaGetSymbolAddress((void**)&g_acc_p, g_acc);
    float* g_vtmp_p;   cudaGetSymbolAddress((void**)&g_vtmp_p, g_vtmp);
    float* g_vfeat_p;  cudaGetSymbolAddress((void**)&g_vfeat_p, g_vfeat);
    float* g_z1_p;     cudaGetSymbolAddress((void**)&g_z1_p, g_z1);
    float* g_z2_p;     cudaGetSymbolAddress((void**)&g_z2_p, g_z2);

    dim3 gemm_node_grid(cdiv(H, 128), cdiv(N_NODES, 128));

    for (int l = 0; l < LAYERS; l++) {
        const float* Wn_l   = Wn + (long)l * H * H;
        const float* bnl_l  = bn_lin + l * H;
        const float* We_l   = We + (long)l * FE * H;
        const float* be_l   = be + l * H;
        const float* res_l  = res_emb + l * H;
        const float* gam_l  = bn_gamma + l * H;
        const float* bet_l  = bn_beta + l * H;

        // x = h + vfeat[gid]
        k_addv<<<cdiv(NH, TPB), TPB>>>(gid);

        // virtual-node segment sum (needs x, must run before x is overwritten)
        if (l < LAYERS - 1) {
            k_vtmp_init<<<cdiv(BH, TPB), TPB>>>();
            k_vseg<<<cdiv(NH, TPB), TPB>>>(gid);
        }

        // hp = x @ Wn + bn_lin
        sgemm_bias<<<gemm_node_grid, 256>>>(g_x_p, Wn_l, bnl_l, g_hp_p,
                                            N_NODES, H, H);
        // acc = relu(hp + res_emb)/deg
        k_resinit<<<cdiv(NH, TPB), TPB>>>(res_l);
        // edge scatter: acc[dst] += norm * relu(hp[src] + ef@We+be)
        k_edge<<<2048, 256>>>(edge_feats, We_l, be_l, src, dst);

        // batch norm over N rows
        k_zero_stats<<<cdiv(H, TPB), TPB>>>(H);
        k_bnstat<<<cdiv(N_NODES, 256), 256>>>(g_acc_p, N_NODES, H);
        k_bnfinal<<<cdiv(H, TPB), TPB>>>(N_NODES, H);
        if (l < LAYERS - 1) {
            k_bnapply<<<cdiv(NH, TPB), TPB>>>(g_acc_p, g_x_p, gam_l, bet_l,
                                              N_NODES, H, 1);
        } else {
            k_bnapply<<<cdiv(NH, TPB), TPB>>>(g_acc_p, (float*)d_out, gam_l,
                                              bet_l, N_NODES, H, 0);
        }

        // virtual-node MLP update
        if (l < LAYERS - 1) {
            const float* vW1_l  = vW1 + (long)l * H * H2;
            const float* vb1_l  = vb1 + l * H2;
            const float* vg1_l  = vg1 + l * H2;
            const float* vbt1_l = vbt1 + l * H2;
            const float* vW2_l  = vW2 + (long)l * H2 * H;
            const float* vb2_l  = vb2 + l * H;
            const float* vg2_l  = vg2 + l * H;
            const float* vbt2_l = vbt2 + l * H;

            dim3 g1(cdiv(H2, 128), cdiv(BGRAPH, 128));
            sgemm_bias<<<g1, 256>>>(g_vtmp_p, vW1_l, vb1_l, g_z1_p,
                                    BGRAPH, H, H2);
            k_zero_stats<<<cdiv(H2, TPB), TPB>>>(H2);
            k_bnstat<<<cdiv(BGRAPH, 256), 256>>>(g_z1_p, BGRAPH, H2);
            k_bnfinal<<<cdiv(H2, TPB), TPB>>>(BGRAPH, H2);
            k_bnapply<<<cdiv(BGRAPH * H2, TPB), TPB>>>(g_z1_p, g_z1_p, vg1_l,
                                                       vbt1_l, BGRAPH, H2, 1);

            dim3 g2(cdiv(H, 128), cdiv(BGRAPH, 128));
            sgemm_bias<<<g2, 256>>>(g_z1_p, vW2_l, vb2_l, g_z2_p,
                                    BGRAPH, H2, H);
            k_zero_stats<<<cdiv(H, TPB), TPB>>>(H);
            k_bnstat<<<cdiv(BGRAPH, 256), 256>>>(g_z2_p, BGRAPH, H);
            k_bnfinal<<<cdiv(H, TPB), TPB>>>(BGRAPH, H);
            k_bnapply<<<cdiv(BH, TPB), TPB>>>(g_z2_p, g_vfeat_p, vg2_l,
                                              vbt2_l, BGRAPH, H, 1);
        }
    }
}

// round 2
// speedup vs baseline: 1.0710x; 1.0710x over previous
#include <cuda_runtime.h>
#include <math.h>

#define N_NODES 100000
#define N_EDGES 260000
#define BGRAPH  4096
#define H       300
#define H2      600
#define LAYERS  5
#define FE      16
#define BN_EPS  1e-5f
#define SCB     ((N_NODES + 1023) / 1024)   // 98 scan blocks

// ---------------- device scratch (static; no runtime allocation) --------------
__device__ float g_x[N_NODES * H];     // h (h_list[l], WITHOUT vfeat add)
__device__ float g_hp[N_NODES * H];    // (h+vfeat[gid]) @ Wn + bn_lin
__device__ float g_acc[N_NODES * H];   // aggregated pre-BN node features
__device__ float g_deg[N_NODES];
__device__ int   g_indeg[N_NODES];
__device__ int   g_cursor[N_NODES];
__device__ int   g_rowptr[N_NODES + 1];
__device__ int   g_part[SCB];
__device__ int   g_csr[N_EDGES];
__device__ int   g_gcnt[BGRAPH];
__device__ float g_vfeat[BGRAPH * H];
__device__ float g_vtmp[BGRAPH * H];   // also reused as z2 buffer
__device__ float g_z1[BGRAPH * H2];
__device__ float g_sum[H2];
__device__ float g_sumsq[H2];
__device__ float g_mean[H2];
__device__ float g_rstd[H2];

static inline int cdiv(int a, int b) { return (a + b - 1) / b; }

// ---------------- init ---------------------------------------------------------

__global__ void k_init0() {
    int i = blockIdx.x * blockDim.x + threadIdx.x;
    if (i < N_NODES) { g_indeg[i] = 0; g_cursor[i] = 0; }
    if (i < BGRAPH) g_gcnt[i] = 0;
}

__global__ void k_count(const int* __restrict__ dst, const int* __restrict__ gid) {
    int i = blockIdx.x * blockDim.x + threadIdx.x;
    if (i < N_EDGES) atomicAdd(&g_indeg[dst[i]], 1);
    if (i < N_NODES) atomicAdd(&g_gcnt[gid[i]], 1);
}

__global__ void k_init3(const float* __restrict__ node_emb,
                        const int* __restrict__ node_types,
                        const float* __restrict__ vn_emb) {
    int idx = blockIdx.x * blockDim.x + threadIdx.x;
    if (idx < N_NODES * H) {
        int n = idx / H, j = idx - n * H;
        g_x[idx] = node_emb[node_types[n] * H + j];
    }
    if (idx < BGRAPH * H) g_vfeat[idx] = vn_emb[idx % H];
    if (idx < N_NODES) g_deg[idx] = (float)g_indeg[idx] + 1.0f;
}

// ---------------- CSR build: scan of indeg ------------------------------------

__global__ void k_scanA() {
    __shared__ int sh[1024];
    int t = threadIdx.x;
    int idx = blockIdx.x * 1024 + t;
    sh[t] = (idx < N_NODES) ? g_indeg[idx] : 0;
    __syncthreads();
    for (int s = 512; s > 0; s >>= 1) {
        if (t < s) sh[t] += sh[t + s];
        __syncthreads();
    }
    if (t == 0) g_part[blockIdx.x] = sh[0];
}

__global__ void k_scanB() {
    int run = 0;
    for (int b = 0; b < SCB; b++) { int v = g_part[b]; g_part[b] = run; run += v; }
    g_rowptr[N_NODES] = run;
}

__global__ void k_scanC() {
    __shared__ int sh[1024];
    int t = threadIdx.x;
    int idx = blockIdx.x * 1024 + t;
    int v = (idx < N_NODES) ? g_indeg[idx] : 0;
    sh[t] = v;
    __syncthreads();
    for (int off = 1; off < 1024; off <<= 1) {
        int x = (t >= off) ? sh[t - off] : 0;
        __syncthreads();
        sh[t] += x;
        __syncthreads();
    }
    if (idx < N_NODES) g_rowptr[idx] = g_part[blockIdx.x] + sh[t] - v;
}

__global__ void k_csrfill(const int* __restrict__ dst) {
    int e = blockIdx.x * blockDim.x + threadIdx.x;
    if (e < N_EDGES) {
        int d = dst[e];
        int pos = g_rowptr[d] + atomicAdd(&g_cursor[d], 1);
        g_csr[pos] = e;
    }
}

// ---------------- virtual node segment sum (analytic vfeat fold) ---------------
// vtmp[b] = segsum(h)[b] + (cnt[b]+1) * vfeat[b]

__global__ void k_vtmp_init() {
    int idx = blockIdx.x * blockDim.x + threadIdx.x;
    if (idx < BGRAPH * H) {
        int b = idx / H;
        g_vtmp[idx] = (float)(g_gcnt[b] + 1) * g_vfeat[idx];
    }
}

__global__ void k_vseg(const int* __restrict__ gid) {
    int idx = blockIdx.x * blockDim.x + threadIdx.x;
    if (idx < N_NODES * H) {
        int n = idx / H, j = idx - n * H;
        atomicAdd(&g_vtmp[gid[n] * H + j], g_x[idx]);
    }
}

// ---------------- GEMM: C[M,N] = (A [+vfeat gather]) @ W + bias ----------------
// BM=128, BN=160, BK=16. 256 threads, 8x10 per-thread tile (cols strided by 16).
__global__ __launch_bounds__(256, 2)
void k_gemm(const float* __restrict__ A, const float* __restrict__ W,
            const float* __restrict__ bias, float* __restrict__ C,
            int M, int K, int Ncol,
            const int* __restrict__ gid, const float* __restrict__ vfeat) {
    __shared__ float As[16][128];
    __shared__ float Bs[16][160];
    int tid = threadIdx.x;
    int tx = tid & 15, ty = tid >> 4;
    int m0 = blockIdx.y * 128, n0 = blockIdx.x * 160;

    float acc[8][10];
#pragma unroll
    for (int i = 0; i < 8; i++)
#pragma unroll
        for (int j = 0; j < 10; j++) acc[i][j] = 0.0f;

    int niter = (K + 15) / 16;
    for (int it = 0; it < niter; it++) {
        int k0 = it * 16;
        // A tile: 128x16, float4 loads (K % 4 == 0 so vectors never straddle)
#pragma unroll
        for (int f = tid; f < 512; f += 256) {
            int r = f >> 2, c4 = (f & 3) << 2;
            int gm = m0 + r, gk = k0 + c4;
            float4 v = make_float4(0.f, 0.f, 0.f, 0.f);
            if (gm < M && gk < K) {
                v = *(const float4*)(A + (size_t)gm * K + gk);
                if (gid) {
                    float4 w = *(const float4*)(vfeat + (size_t)gid[gm] * K + gk);
                    v.x += w.x; v.y += w.y; v.z += w.z; v.w += w.w;
                }
            }
            As[c4 + 0][r] = v.x; As[c4 + 1][r] = v.y;
            As[c4 + 2][r] = v.z; As[c4 + 3][r] = v.w;
        }
        // B tile: 16x160, float4 loads (Ncol % 4 == 0)
#pragma unroll
        for (int f = tid; f < 640; f += 256) {
            int kr = f / 40, c4 = (f % 40) << 2;
            int gk = k0 + kr, gn = n0 + c4;
            float4 v = make_float4(0.f, 0.f, 0.f, 0.f);
            if (gk < K && gn < Ncol)
                v = *(const float4*)(W + (size_t)gk * Ncol + gn);
            *(float4*)&Bs[kr][c4] = v;
        }
        __syncthreads();
#pragma unroll
        for (int kk = 0; kk < 16; kk++) {
            float ra[8], rb[10];
#pragma unroll
            for (int i = 0; i < 8; i++) ra[i] = As[kk][ty * 8 + i];
#pragma unroll
            for (int j = 0; j < 10; j++) rb[j] = Bs[kk][tx + 16 * j];
#pragma unroll
            for (int i = 0; i < 8; i++)
#pragma unroll
                for (int j = 0; j < 10; j++)
                    acc[i][j] = fmaf(ra[i], rb[j], acc[i][j]);
        }
        __syncthreads();
    }
#pragma unroll
    for (int j = 0; j < 10; j++) {
        int gn = n0 + tx + 16 * j;
        if (gn >= Ncol) continue;
        float b = bias[gn];
#pragma unroll
        for (int i = 0; i < 8; i++) {
            int gm = m0 + ty * 8 + i;
            if (gm < M) C[(size_t)gm * Ncol + gn] = acc[i][j] + b;
        }
    }
}

// ---------------- fused node aggregation --------------------------------------
// warp per node: acc[n] = relu(hp[n]+res)/deg[n] + sum_e norm_e*relu(hp[src]+ep_e)
// ep computed on the fly (We in smem); BN stats accumulated in registers.
__global__ __launch_bounds__(256)
void k_agg(const float* __restrict__ ef, const float* __restrict__ We_l,
           const float* __restrict__ be_l, const float* __restrict__ res_l,
           const int* __restrict__ src) {
    __shared__ float Ws[FE * H];
    __shared__ float Bsh[H];
    for (int i = threadIdx.x; i < FE * H; i += 256) Ws[i] = We_l[i];
    for (int i = threadIdx.x; i < H; i += 256) Bsh[i] = be_l[i];
    __syncthreads();

    int lane = threadIdx.x & 31;
    int gw = (blockIdx.x * 256 + threadIdx.x) >> 5;
    int nw = (gridDim.x * 256) >> 5;

    float ls[10], lq[10];
#pragma unroll
    for (int t = 0; t < 10; t++) { ls[t] = 0.f; lq[t] = 0.f; }

    for (int n = gw; n < N_NODES; n += nw) {
        float dn = g_deg[n];
        float a[10];
#pragma unroll
        for (int t = 0; t < 10; t++) {
            int j = lane + 32 * t;
            a[t] = (j < H) ? fmaxf(g_hp[(size_t)n * H + j] + res_l[j], 0.f) / dn
                           : 0.f;
        }
        int e0 = g_rowptr[n], e1 = g_rowptr[n + 1];
        for (int e = e0; e < e1; e++) {
            int eid = g_csr[e];
            int s = src[eid];
            float nrm = rsqrtf(g_deg[s] * dn);
            float ev = (lane < FE) ? ef[(size_t)eid * FE + lane] : 0.f;
            float ek[16];
#pragma unroll
            for (int k = 0; k < 16; k++) ek[k] = __shfl_sync(0xffffffffu, ev, k);
            const float* hs = g_hp + (size_t)s * H;
#pragma unroll
            for (int t = 0; t < 10; t++) {
                int j = lane + 32 * t;
                if (j < H) {
                    float ep = Bsh[j];
#pragma unroll
                    for (int k = 0; k < 16; k++)
                        ep = fmaf(ek[k], Ws[k * H + j], ep);
                    a[t] += nrm * fmaxf(hs[j] + ep, 0.f);
                }
            }
        }
#pragma unroll
        for (int t = 0; t < 10; t++) {
            int j = lane + 32 * t;
            if (j < H) {
                g_acc[(size_t)n * H + j] = a[t];
                ls[t] += a[t];
                lq[t] += a[t] * a[t];
            }
        }
    }
#pragma unroll
    for (int t = 0; t < 10; t++) {
        int j = lane + 32 * t;
        if (j < H) {
            atomicAdd(&g_sum[j], ls[t]);
            atomicAdd(&g_sumsq[j], lq[t]);
        }
    }
}

// ---------------- batch norm ---------------------------------------------------

__global__ void k_zero_stats(int cols) {
    int c = blockIdx.x * blockDim.x + threadIdx.x;
    if (c < cols) { g_sum[c] = 0.0f; g_sumsq[c] = 0.0f; }
}

__global__ void k_bnstat(const float* __restrict__ X, int rows, int cols) {
    int r0 = blockIdx.x * 256;
    int rend = min(r0 + 256, rows);
    int t = threadIdx.x;
    float s[3] = {0, 0, 0}, q[3] = {0, 0, 0};
    for (int r = r0; r < rend; r++) {
        const float* row = X + (size_t)r * cols;
        int ci = 0;
        for (int c = t; c < cols; c += 256, ci++) {
            float v = row[c];
            s[ci] += v; q[ci] += v * v;
        }
    }
    int ci = 0;
    for (int c = t; c < cols; c += 256, ci++) {
        atomicAdd(&g_sum[c], s[ci]);
        atomicAdd(&g_sumsq[c], q[ci]);
    }
}

__global__ void k_bnfinal(int rows, int cols) {
    int c = blockIdx.x * blockDim.x + threadIdx.x;
    if (c < cols) {
        float m = g_sum[c] / (float)rows;
        float v = g_sumsq[c] / (float)rows - m * m;
        g_mean[c] = m;
        g_rstd[c] = rsqrtf(v + BN_EPS);
    }
}

__global__ void k_bnapply(const float* __restrict__ X, float* __restrict__ Y,
                          const float* __restrict__ gamma,
                          const float* __restrict__ beta,
                          int rows, int cols, int do_relu) {
    int idx = blockIdx.x * blockDim.x + threadIdx.x;
    if (idx < rows * cols) {
        int c = idx % cols;
        float v = (X[idx] - g_mean[c]) * g_rstd[c] * gamma[c] + beta[c];
        if (do_relu) v = fmaxf(v, 0.0f);
        Y[idx] = v;
    }
}

// ---------------- host orchestration -------------------------------------------

extern "C" void kernel_launch(void* const* d_in, const int* in_sizes, int n_in,
                              void* d_out, int out_size) {
    const int *node_types, *src, *dst, *gid;
    const float *edge_feats, *node_emb, *Wn, *bn_lin, *We, *be, *res_emb,
                *bn_gamma, *bn_beta, *vn_emb, *vW1, *vb1, *vg1, *vbt1,
                *vW2, *vb2, *vg2, *vbt2;

    if (in_sizes[0] == N_NODES) {
        node_types = (const int*)d_in[0];
        edge_feats = (const float*)d_in[1];
        src        = (const int*)d_in[2];
        dst        = (const int*)d_in[3];
        gid        = (const int*)d_in[4];
        node_emb = (const float*)d_in[6];
        Wn       = (const float*)d_in[7];
        bn_lin   = (const float*)d_in[8];
        We       = (const float*)d_in[9];
        be       = (const float*)d_in[10];
        res_emb  = (const float*)d_in[11];
        bn_gamma = (const float*)d_in[12];
        bn_beta  = (const float*)d_in[13];
        vn_emb   = (const float*)d_in[14];
        vW1  = (const float*)d_in[15];
        vb1  = (const float*)d_in[16];
        vg1  = (const float*)d_in[17];
        vbt1 = (const float*)d_in[18];
        vW2  = (const float*)d_in[19];
        vb2  = (const float*)d_in[20];
        vg2  = (const float*)d_in[21];
        vbt2 = (const float*)d_in[22];
    } else {
        edge_feats = (const float*)d_in[0];
        node_emb = (const float*)d_in[1];
        Wn       = (const float*)d_in[2];
        bn_lin   = (const float*)d_in[3];
        We       = (const float*)d_in[4];
        be       = (const float*)d_in[5];
        res_emb  = (const float*)d_in[6];
        bn_gamma = (const float*)d_in[7];
        bn_beta  = (const float*)d_in[8];
        vn_emb   = (const float*)d_in[9];
        vW1  = (const float*)d_in[10];
        vb1  = (const float*)d_in[11];
        vg1  = (const float*)d_in[12];
        vbt1 = (const float*)d_in[13];
        vW2  = (const float*)d_in[14];
        vb2  = (const float*)d_in[15];
        vg2  = (const float*)d_in[16];
        vbt2 = (const float*)d_in[17];
        node_types = (const int*)d_in[18];
        src        = (const int*)d_in[19];
        dst        = (const int*)d_in[20];
        gid        = (const int*)d_in[21];
    }

    const int NH = N_NODES * H;
    const int BH = BGRAPH * H;
    const int TPB = 256;

    float *g_x_p, *g_hp_p, *g_acc_p, *g_vtmp_p, *g_vfeat_p, *g_z1_p;
    cudaGetSymbolAddress((void**)&g_x_p, g_x);
    cudaGetSymbolAddress((void**)&g_hp_p, g_hp);
    cudaGetSymbolAddress((void**)&g_acc_p, g_acc);
    cudaGetSymbolAddress((void**)&g_vtmp_p, g_vtmp);
    cudaGetSymbolAddress((void**)&g_vfeat_p, g_vfeat);
    cudaGetSymbolAddress((void**)&g_z1_p, g_z1);

    // --- init + CSR build (graph static across layers) ---
    k_init0<<<cdiv(N_NODES, TPB), TPB>>>();
    k_count<<<cdiv(N_EDGES, TPB), TPB>>>(dst, gid);
    k_init3<<<cdiv(NH, TPB), TPB>>>(node_emb, node_types, vn_emb);
    k_scanA<<<SCB, 1024>>>();
    k_scanB<<<1, 1>>>();
    k_scanC<<<SCB, 1024>>>();
    k_csrfill<<<cdiv(N_EDGES, TPB), TPB>>>(dst);

    dim3 node_grid(2, cdiv(N_NODES, 128));   // 320 cols cover H=300

    for (int l = 0; l < LAYERS; l++) {
        const float* Wn_l  = Wn + (size_t)l * H * H;
        const float* bnl_l = bn_lin + l * H;
        const float* We_l  = We + (size_t)l * FE * H;
        const float* be_l  = be + l * H;
        const float* res_l = res_emb + l * H;
        const float* gam_l = bn_gamma + l * H;
        const float* bet_l = bn_beta + l * H;

        // virtual-node segment sum (analytic vfeat fold; reads h = g_x)
        if (l < LAYERS - 1) {
            k_vtmp_init<<<cdiv(BH, TPB), TPB>>>();
            k_vseg<<<cdiv(NH, TPB), TPB>>>(gid);
        }

        // hp = (h + vfeat[gid]) @ Wn + bn_lin
        k_gemm<<<node_grid, 256>>>(g_x_p, Wn_l, bnl_l, g_hp_p,
                                   N_NODES, H, H, gid, g_vfeat_p);

        // fused: res init + edge messages + aggregation + BN stats
        k_zero_stats<<<cdiv(H, TPB), TPB>>>(H);
        k_agg<<<592, 256>>>(edge_feats, We_l, be_l, res_l, src);
        k_bnfinal<<<cdiv(H, TPB), TPB>>>(N_NODES, H);
        if (l < LAYERS - 1) {
            k_bnapply<<<cdiv(NH, TPB), TPB>>>(g_acc_p, g_x_p, gam_l, bet_l,
                                              N_NODES, H, 1);
        } else {
            k_bnapply<<<cdiv(NH, TPB), TPB>>>(g_acc_p, (float*)d_out, gam_l,
                                              bet_l, N_NODES, H, 0);
        }

        // virtual-node MLP update
        if (l < LAYERS - 1) {
            const float* vW1_l  = vW1 + (size_t)l * H * H2;
            const float* vb1_l  = vb1 + l * H2;
            const float* vg1_l  = vg1 + l * H2;
            const float* vbt1_l = vbt1 + l * H2;
            const float* vW2_l  = vW2 + (size_t)l * H2 * H;
            const float* vb2_l  = vb2 + l * H;
            const float* vg2_l  = vg2 + l * H;
            const float* vbt2_l = vbt2 + l * H;

            dim3 g1(4, cdiv(BGRAPH, 128));   // 640 cols cover H2=600
            k_gemm<<<g1, 256>>>(g_vtmp_p, vW1_l, vb1_l, g_z1_p,
                                BGRAPH, H, H2, nullptr, nullptr);
            k_zero_stats<<<cdiv(H2, TPB), TPB>>>(H2);
            k_bnstat<<<cdiv(BGRAPH, 256), 256>>>(g_z1_p, BGRAPH, H2);
            k_bnfinal<<<cdiv(H2, TPB), TPB>>>(BGRAPH, H2);
            k_bnapply<<<cdiv(BGRAPH * H2, TPB), TPB>>>(g_z1_p, g_z1_p, vg1_l,
                                                       vbt1_l, BGRAPH, H2, 1);

            dim3 g2(2, cdiv(BGRAPH, 128));
            k_gemm<<<g2, 256>>>(g_z1_p, vW2_l, vb2_l, g_vtmp_p,
                                BGRAPH, H2, H, nullptr, nullptr);
            k_zero_stats<<<cdiv(H, TPB), TPB>>>(H);
            k_bnstat<<<cdiv(BGRAPH, 256), 256>>>(g_vtmp_p, BGRAPH, H);
            k_bnfinal<<<cdiv(H, TPB), TPB>>>(BGRAPH, H);
            k_bnapply<<<cdiv(BH, TPB), TPB>>>(g_vtmp_p, g_vfeat_p, vg2_l,
                                              vbt2_l, BGRAPH, H, 1);
        }
    }
}